// round 1
// baseline (speedup 1.0000x reference)
#include <cuda_runtime.h>
#include <math.h>

#define B_SZ   4
#define LEN_Q  21760
#define LEN_IN 21760
#define NQ     (B_SZ * LEN_Q)     // 87040
#define DM     256

// Scratch (allocation-free rule: __device__ globals)
__device__ float g_value[(size_t)NQ * DM];      // [B, Lin, 8, 32]  89 MB
__device__ float g_offattn[(size_t)NQ * 384];   // [B*Lq, 256 off | 128 attn]  134 MB
__device__ float g_outcore[(size_t)NQ * DM];    // [B*Lq, 256]  89 MB

// ---------------------------------------------------------------------------
// Tiled fp32 GEMM: C[M,N] = A[M,K] @ B[K,N] + bias[N]
// Block tile 64x64, K-step 16, 256 threads, 4x4 per-thread microtile.
// Requires M%64==0, N%64==0, K%16==0 (true for all calls here).
// ---------------------------------------------------------------------------
__global__ __launch_bounds__(256)
void gemm64_bias(const float* __restrict__ A, const float* __restrict__ Bm,
                 const float* __restrict__ bias, float* __restrict__ C,
                 int K, int N, int ldc)
{
    __shared__ float As[16][64];
    __shared__ float Bs[16][64];

    const int t  = threadIdx.x;
    const int bm = blockIdx.y << 6;
    const int bn = blockIdx.x << 6;
    const int tx = t & 15, ty = t >> 4;

    const int arow = t >> 2;        // 0..63
    const int ak   = (t & 3) << 2;  // 0,4,8,12
    const int brow = t >> 4;        // 0..15
    const int bcol = (t & 15) << 2; // 0..60

    float acc[4][4] = {};

    const float* Aptr = A + (size_t)(bm + arow) * K + ak;
    const float* Bptr = Bm + (size_t)brow * N + bn + bcol;

    for (int k0 = 0; k0 < K; k0 += 16) {
        float4 av = *(const float4*)(Aptr + k0);
        As[ak + 0][arow] = av.x;
        As[ak + 1][arow] = av.y;
        As[ak + 2][arow] = av.z;
        As[ak + 3][arow] = av.w;
        float4 bv = *(const float4*)(Bptr + (size_t)k0 * N);
        *(float4*)&Bs[brow][bcol] = bv;
        __syncthreads();

        #pragma unroll
        for (int k = 0; k < 16; ++k) {
            float4 a = *(const float4*)&As[k][ty << 2];
            float4 b = *(const float4*)&Bs[k][tx << 2];
            acc[0][0] += a.x * b.x; acc[0][1] += a.x * b.y;
            acc[0][2] += a.x * b.z; acc[0][3] += a.x * b.w;
            acc[1][0] += a.y * b.x; acc[1][1] += a.y * b.y;
            acc[1][2] += a.y * b.z; acc[1][3] += a.y * b.w;
            acc[2][0] += a.z * b.x; acc[2][1] += a.z * b.y;
            acc[2][2] += a.z * b.z; acc[2][3] += a.z * b.w;
            acc[3][0] += a.w * b.x; acc[3][1] += a.w * b.y;
            acc[3][2] += a.w * b.z; acc[3][3] += a.w * b.w;
        }
        __syncthreads();
    }

    float4 bb = *(const float4*)&bias[bn + (tx << 2)];
    #pragma unroll
    for (int i = 0; i < 4; ++i) {
        float4 o;
        o.x = acc[i][0] + bb.x;
        o.y = acc[i][1] + bb.y;
        o.z = acc[i][2] + bb.z;
        o.w = acc[i][3] + bb.w;
        *(float4*)&C[(size_t)(bm + (ty << 2) + i) * ldc + bn + (tx << 2)] = o;
    }
}

// ---------------------------------------------------------------------------
// Deformable sampling: one block per query, one warp per head, lane = channel.
// Reads g_offattn (offsets + attn logits), softmaxes 16 logits per head in-warp,
// bilinear-gathers from g_value with zeros padding, writes g_outcore.
// ---------------------------------------------------------------------------
__global__ __launch_bounds__(256)
void msda_sample(const float* __restrict__ value,    // [B, Lin, 8, 32]
                 const float* __restrict__ offattn,  // [B*Lq, 384]
                 const float* __restrict__ refpts,   // [B, Lq, 4, 2]
                 const int*   __restrict__ spatial,  // [4, 2] (H, W)
                 const int*   __restrict__ lstart,   // [4]
                 float* __restrict__ outcore)        // [B*Lq, 256]
{
    const int qg   = blockIdx.x;           // b*LEN_Q + q
    const int b    = qg / LEN_Q;
    const int head = threadIdx.x >> 5;
    const int lane = threadIdx.x & 31;

    __shared__ float s_ref[8];
    __shared__ int   s_H[4], s_W[4], s_start[4];
    if (threadIdx.x < 4) {
        s_H[threadIdx.x]     = spatial[2 * threadIdx.x];
        s_W[threadIdx.x]     = spatial[2 * threadIdx.x + 1];
        s_start[threadIdx.x] = lstart[threadIdx.x];
    }
    if (threadIdx.x < 8)
        s_ref[threadIdx.x] = refpts[(size_t)qg * 8 + threadIdx.x];
    __syncthreads();

    const float* oa  = offattn + (size_t)qg * 384;
    const float* off = oa + head * 32;             // [4 levels][4 pts][2]

    // softmax over the 16 attention logits of this head (lanes 0..15)
    float logit = (lane < 16) ? oa[256 + head * 16 + lane] : -1e30f;
    float mx = logit;
    #pragma unroll
    for (int d = 8; d; d >>= 1) mx = fmaxf(mx, __shfl_xor_sync(0xffffffffu, mx, d));
    float e = (lane < 16) ? expf(logit - mx) : 0.f;
    float sum = e;
    #pragma unroll
    for (int d = 8; d; d >>= 1) sum += __shfl_xor_sync(0xffffffffu, sum, d);
    float w = e / sum;

    const float* vbase = value + (size_t)b * LEN_IN * 256 + head * 32 + lane;

    float acc = 0.f;
    #pragma unroll
    for (int s = 0; s < 16; ++s) {
        const int l = s >> 2;
        const float aw = __shfl_sync(0xffffffffu, w, s);

        const int   H = s_H[l], W = s_W[l], start = s_start[l];
        const float Hf = (float)H, Wf = (float)W;

        const float ox = __ldg(&off[2 * s]);       // uniform across warp
        const float oy = __ldg(&off[2 * s + 1]);
        const float lx = s_ref[2 * l]     + ox / Wf;
        const float ly = s_ref[2 * l + 1] + oy / Hf;

        const float x = lx * Wf - 0.5f;
        const float y = ly * Hf - 0.5f;
        const float x0f = floorf(x), y0f = floorf(y);
        const float fx = x - x0f, fy = y - y0f;
        const int x0 = (int)x0f, y0 = (int)y0f;

        float samp = 0.f;
        #pragma unroll
        for (int dy = 0; dy < 2; ++dy) {
            const int yi = y0 + dy;
            if (yi < 0 || yi >= H) continue;
            const float wy = dy ? fy : (1.f - fy);
            #pragma unroll
            for (int dx = 0; dx < 2; ++dx) {
                const int xi = x0 + dx;
                if (xi < 0 || xi >= W) continue;
                const float wx = dx ? fx : (1.f - fx);
                const size_t idx = (size_t)start + (size_t)yi * W + xi;
                samp += wx * wy * __ldg(vbase + idx * 256);
            }
        }
        acc += aw * samp;
    }

    outcore[(size_t)qg * 256 + head * 32 + lane] = acc;
}

// ---------------------------------------------------------------------------
extern "C" void kernel_launch(void* const* d_in, const int* in_sizes, int n_in,
                              void* d_out, int out_size)
{
    const float* query   = (const float*)d_in[0];
    const float* refpts  = (const float*)d_in[1];
    const float* input   = (const float*)d_in[2];
    const int*   spatial = (const int*)  d_in[3];
    const int*   lstart  = (const int*)  d_in[4];
    const float* W_off   = (const float*)d_in[5];
    const float* b_off   = (const float*)d_in[6];
    const float* W_attn  = (const float*)d_in[7];
    const float* b_attn  = (const float*)d_in[8];
    const float* W_val   = (const float*)d_in[9];
    const float* b_val   = (const float*)d_in[10];
    const float* W_out   = (const float*)d_in[11];
    const float* b_out   = (const float*)d_in[12];
    float* out = (float*)d_out;

    float *value, *offattn, *outcore;
    cudaGetSymbolAddress((void**)&value,   g_value);
    cudaGetSymbolAddress((void**)&offattn, g_offattn);
    cudaGetSymbolAddress((void**)&outcore, g_outcore);

    const dim3 blk(256);
    const int MT = NQ / 64;  // 1360

    // value projection: [NQ,256] = input @ W_val + b_val
    gemm64_bias<<<dim3(4, MT), blk>>>(input, W_val, b_val, value, 256, 256, 256);
    // offsets: cols [0,256) of g_offattn
    gemm64_bias<<<dim3(4, MT), blk>>>(query, W_off, b_off, offattn, 256, 256, 384);
    // attn logits: cols [256,384)
    gemm64_bias<<<dim3(2, MT), blk>>>(query, W_attn, b_attn, offattn + 256, 256, 128, 384);
    // deformable bilinear sampling + softmax-weighted sum
    msda_sample<<<NQ, blk>>>(value, offattn, refpts, spatial, lstart, outcore);
    // output projection
    gemm64_bias<<<dim3(4, MT), blk>>>(outcore, W_out, b_out, out, 256, 256, 256);
}

// round 3
// speedup vs baseline: 5.8791x; 5.8791x over previous
#include <cuda_runtime.h>
#include <cstdint>
#include <math.h>

#define B_SZ   4
#define LEN_Q  21760
#define LEN_IN 21760
#define NQ     (B_SZ * LEN_Q)     // 87040
#define DM     256

// Scratch (allocation-free rule: __device__ globals)
__device__ float g_value[(size_t)NQ * DM];      // [B, Lin, 8, 32]
__device__ float g_offattn[(size_t)NQ * 384];   // [B*Lq, 256 off | 128 attn]
__device__ float g_outcore[(size_t)NQ * DM];    // [B*Lq, 256]
__device__ float g_wt[4 * 256 * 256];           // transposed weights [N,K]

// ---------------------------------------------------------------------------
// helpers
// ---------------------------------------------------------------------------
__device__ __forceinline__ uint32_t smem_u32(const void* p) {
    uint32_t a;
    asm("{ .reg .u64 t; cvta.to.shared.u64 t, %1; cvt.u32.u64 %0, t; }"
        : "=r"(a) : "l"(p));
    return a;
}
__device__ __forceinline__ void cp16(uint32_t dst, const void* src) {
    asm volatile("cp.async.ca.shared.global [%0], [%1], 16;"
                 :: "r"(dst), "l"(src) : "memory");
}
#define CP_COMMIT() asm volatile("cp.async.commit_group;" ::: "memory")
#define CP_WAIT(n)  asm volatile("cp.async.wait_group %0;" :: "n"(n) : "memory")

__device__ __forceinline__ uint32_t lds_tf32(uint32_t addr) {
    float v; uint32_t r;
    asm volatile("ld.shared.f32 %0, [%1];" : "=f"(v) : "r"(addr));
    asm("cvt.rna.tf32.f32 %0, %1;" : "=r"(r) : "f"(v));
    return r;
}
__device__ __forceinline__ void mma_tf32(float* c, const uint32_t* a, const uint32_t* b) {
    asm volatile(
        "mma.sync.aligned.m16n8k8.row.col.f32.tf32.tf32.f32 "
        "{%0,%1,%2,%3}, {%4,%5,%6,%7}, {%8,%9}, {%0,%1,%2,%3};"
        : "+f"(c[0]), "+f"(c[1]), "+f"(c[2]), "+f"(c[3])
        : "r"(a[0]), "r"(a[1]), "r"(a[2]), "r"(a[3]), "r"(b[0]), "r"(b[1]));
}

// ---------------------------------------------------------------------------
// Weight transpose: dst[N,K] <- src[K,N]
// ---------------------------------------------------------------------------
__global__ void transpose_w(const float* __restrict__ src, float* __restrict__ dst,
                            int K, int N)
{
    __shared__ float t[32][33];
    const int n0 = blockIdx.x << 5, k0 = blockIdx.y << 5;
    const int tx = threadIdx.x, ty = threadIdx.y;
    #pragma unroll
    for (int i = 0; i < 4; ++i)
        t[ty + 8 * i][tx] = src[(size_t)(k0 + ty + 8 * i) * N + n0 + tx];
    __syncthreads();
    #pragma unroll
    for (int i = 0; i < 4; ++i)
        dst[(size_t)(n0 + ty + 8 * i) * K + k0 + tx] = t[tx][ty + 8 * i];
}

// ---------------------------------------------------------------------------
// mma.sync tf32 GEMM: C[M, *] tile = A[M,256] @ Bt[N,256]^T + bias
// CTA tile 128x128, 8 warps (2M x 4N), warp tile 64x32, k-chunks of 32,
// cp.async double-buffered. Smem pitch 36 floats -> conflict-free LDS.
// ---------------------------------------------------------------------------
#define PITCH 36
#define STAGE_F (128 * PITCH)          // floats per (A or B) stage

__global__ __launch_bounds__(256, 2)
void gemm_mma(const float* __restrict__ A, const float* __restrict__ Bt,
              const float* __restrict__ bias, float* __restrict__ C, int ldc)
{
    extern __shared__ float sm[];
    const int tid = threadIdx.x, wid = tid >> 5, lane = tid & 31;
    const int bm = blockIdx.x << 7;
    const int bn = blockIdx.y << 7;
    const int wm = (wid >> 2) << 6;     // 0 / 64
    const int wn = (wid & 3) << 5;      // 0..96

    const float* Ag = A  + (size_t)bm * 256;
    const float* Bg = Bt + (size_t)bn * 256;
    const uint32_t sb = smem_u32(sm);

    // stage s: A at s*2*STAGE_F, B at (s*2+1)*STAGE_F  (floats)
    auto load = [&](int c, int s) {
        const int k0 = c * 32;
        const uint32_t sa = sb + (uint32_t)(s * 2) * STAGE_F * 4;
        const uint32_t sbB = sb + (uint32_t)(s * 2 + 1) * STAGE_F * 4;
        #pragma unroll
        for (int i = 0; i < 4; ++i) {
            int f = tid + i * 256;
            int row = f >> 3, c4 = (f & 7) * 4;
            cp16(sa  + (uint32_t)(row * PITCH + c4) * 4, Ag + (size_t)row * 256 + k0 + c4);
            cp16(sbB + (uint32_t)(row * PITCH + c4) * 4, Bg + (size_t)row * 256 + k0 + c4);
        }
        CP_COMMIT();
    };

    float acc[4][4][4] = {};

    load(0, 0);
    load(1, 1);

    const int gm = lane >> 2, gk = lane & 3;

    #pragma unroll
    for (int ch = 0; ch < 8; ++ch) {
        const int s = ch & 1;
        if (ch == 7) CP_WAIT(0); else CP_WAIT(1);
        __syncthreads();

        const uint32_t sa  = sb + (uint32_t)(s * 2) * STAGE_F * 4;
        const uint32_t sbB = sb + (uint32_t)(s * 2 + 1) * STAGE_F * 4;

        #pragma unroll
        for (int kk = 0; kk < 4; ++kk) {
            const int kb = kk * 8 + gk;
            uint32_t afr[4][4], bfr[4][2];
            #pragma unroll
            for (int mt = 0; mt < 4; ++mt) {
                const uint32_t base = sa + (uint32_t)((wm + mt * 16 + gm) * PITCH + kb) * 4;
                afr[mt][0] = lds_tf32(base);
                afr[mt][1] = lds_tf32(base + 8 * PITCH * 4);
                afr[mt][2] = lds_tf32(base + 16);
                afr[mt][3] = lds_tf32(base + 8 * PITCH * 4 + 16);
            }
            #pragma unroll
            for (int nt = 0; nt < 4; ++nt) {
                const uint32_t base = sbB + (uint32_t)((wn + nt * 8 + gm) * PITCH + kb) * 4;
                bfr[nt][0] = lds_tf32(base);
                bfr[nt][1] = lds_tf32(base + 16);
            }
            #pragma unroll
            for (int mt = 0; mt < 4; ++mt)
                #pragma unroll
                for (int nt = 0; nt < 4; ++nt)
                    mma_tf32(acc[mt][nt], afr[mt], bfr[nt]);
        }
        __syncthreads();
        if (ch + 2 < 8) load(ch + 2, s);
    }

    // epilogue
    const int gn2 = (lane & 3) * 2;
    #pragma unroll
    for (int nt = 0; nt < 4; ++nt) {
        const int col = bn + wn + nt * 8 + gn2;
        const float b0 = bias[col], b1 = bias[col + 1];
        #pragma unroll
        for (int mt = 0; mt < 4; ++mt) {
            const int r0 = bm + wm + mt * 16 + gm;
            float2 o0 = { acc[mt][nt][0] + b0, acc[mt][nt][1] + b1 };
            float2 o1 = { acc[mt][nt][2] + b0, acc[mt][nt][3] + b1 };
            *(float2*)(C + (size_t)r0 * ldc + col) = o0;
            *(float2*)(C + (size_t)(r0 + 8) * ldc + col) = o1;
        }
    }
}

// ---------------------------------------------------------------------------
// Deformable sampling v2: block = 1 query (128 threads, 4 warps).
// Warp w serves heads 2w, 2w+1; lane = (head-half, float2-of-channels).
// Setup phase: 32 lanes compute the 32 (head,sample) parameter sets in
// parallel (softmax + bilinear weights + clamped corner indices) -> smem.
// Gather phase: per sample 2x LDS.128 + 4x LDG.64 + 8 FFMA.
// ---------------------------------------------------------------------------
__global__ __launch_bounds__(128)
void msda_sample2(const float* __restrict__ value,    // [B, Lin, 8, 32]
                  const float* __restrict__ offattn,  // [B*Lq, 384]
                  const float* __restrict__ refpts,   // [B, Lq, 4, 2]
                  const int*   __restrict__ spatial,  // [4, 2]
                  const int*   __restrict__ lstart,   // [4]
                  float* __restrict__ outcore)        // [B*Lq, 256]
{
    const int qg  = blockIdx.x;
    const int b   = qg / LEN_Q;
    const int tid = threadIdx.x, wid = tid >> 5, lane = tid & 31;

    __shared__ float s_ref[8];
    __shared__ int   s_H[4], s_W[4], s_S[4];
    __shared__ __align__(16) float s_par[8][17][8];   // [head][sample][4 idx | 4 w]

    if (tid < 4) {
        s_H[tid] = spatial[2 * tid];
        s_W[tid] = spatial[2 * tid + 1];
        s_S[tid] = lstart[tid];
    }
    if (tid < 8) s_ref[tid] = refpts[(size_t)qg * 8 + tid];
    __syncthreads();

    const float* oa = offattn + (size_t)qg * 384;

    // ---- setup: one (head, sample) per lane ----
    {
        const int hh = lane >> 4, s = lane & 15;
        const int head = 2 * wid + hh, l = s >> 2;

        float logit = oa[256 + head * 16 + s];
        float mx = logit;
        #pragma unroll
        for (int d = 8; d; d >>= 1) mx = fmaxf(mx, __shfl_xor_sync(0xffffffffu, mx, d));
        float e = expf(logit - mx);
        float sum = e;
        #pragma unroll
        for (int d = 8; d; d >>= 1) sum += __shfl_xor_sync(0xffffffffu, sum, d);
        const float aw = e / sum;

        const int H = s_H[l], W = s_W[l], st = s_S[l];
        const float Wf = (float)W, Hf = (float)H;
        const float ox = oa[head * 32 + 2 * s];
        const float oy = oa[head * 32 + 2 * s + 1];
        const float lx = s_ref[2 * l]     + ox / Wf;
        const float ly = s_ref[2 * l + 1] + oy / Hf;
        const float x = lx * Wf - 0.5f;
        const float y = ly * Hf - 0.5f;
        const float x0f = floorf(x), y0f = floorf(y);
        const float fx = x - x0f, fy = y - y0f;
        const int x0 = (int)x0f, y0 = (int)y0f;
        const int x1 = x0 + 1, y1 = y0 + 1;

        const float vx0 = (x0 >= 0 && x0 < W) ? 1.f : 0.f;
        const float vx1 = (x1 >= 0 && x1 < W) ? 1.f : 0.f;
        const float vy0 = (y0 >= 0 && y0 < H) ? 1.f : 0.f;
        const float vy1 = (y1 >= 0 && y1 < H) ? 1.f : 0.f;
        const int cx0 = min(max(x0, 0), W - 1), cx1 = min(max(x1, 0), W - 1);
        const int cy0 = min(max(y0, 0), H - 1), cy1 = min(max(y1, 0), H - 1);

        float* p = s_par[head][s];
        p[0] = __int_as_float(st + cy0 * W + cx0);
        p[1] = __int_as_float(st + cy0 * W + cx1);
        p[2] = __int_as_float(st + cy1 * W + cx0);
        p[3] = __int_as_float(st + cy1 * W + cx1);
        p[4] = aw * (1.f - fx) * (1.f - fy) * vx0 * vy0;
        p[5] = aw * fx * (1.f - fy) * vx1 * vy0;
        p[6] = aw * (1.f - fx) * fy * vx0 * vy1;
        p[7] = aw * fx * fy * vx1 * vy1;
    }
    __syncwarp();

    // ---- gather ----
    const int hh = lane >> 4, head = 2 * wid + hh, ch2 = lane & 15;
    const float2* vb = (const float2*)(value + (size_t)b * LEN_IN * 256 + head * 32) + ch2;

    float ax = 0.f, ay = 0.f;
    #pragma unroll
    for (int s = 0; s < 16; ++s) {
        const float4 pi = *(const float4*)&s_par[head][s][0];
        const float4 pw = *(const float4*)&s_par[head][s][4];
        const float2 v0 = vb[(size_t)__float_as_int(pi.x) * 128];
        const float2 v1 = vb[(size_t)__float_as_int(pi.y) * 128];
        const float2 v2 = vb[(size_t)__float_as_int(pi.z) * 128];
        const float2 v3 = vb[(size_t)__float_as_int(pi.w) * 128];
        ax += pw.x * v0.x + pw.y * v1.x + pw.z * v2.x + pw.w * v3.x;
        ay += pw.x * v0.y + pw.y * v1.y + pw.z * v2.y + pw.w * v3.y;
    }
    float2 o = { ax, ay };
    *(float2*)(outcore + (size_t)qg * 256 + head * 32 + 2 * ch2) = o;
}

// ---------------------------------------------------------------------------
extern "C" void kernel_launch(void* const* d_in, const int* in_sizes, int n_in,
                              void* d_out, int out_size)
{
    const float* query   = (const float*)d_in[0];
    const float* refpts  = (const float*)d_in[1];
    const float* input   = (const float*)d_in[2];
    const int*   spatial = (const int*)  d_in[3];
    const int*   lstart  = (const int*)  d_in[4];
    const float* W_off   = (const float*)d_in[5];
    const float* b_off   = (const float*)d_in[6];
    const float* W_attn  = (const float*)d_in[7];
    const float* b_attn  = (const float*)d_in[8];
    const float* W_val   = (const float*)d_in[9];
    const float* b_val   = (const float*)d_in[10];
    const float* W_out   = (const float*)d_in[11];
    const float* b_out   = (const float*)d_in[12];
    float* out = (float*)d_out;

    float *value, *offattn, *outcore, *wt;
    cudaGetSymbolAddress((void**)&value,   g_value);
    cudaGetSymbolAddress((void**)&offattn, g_offattn);
    cudaGetSymbolAddress((void**)&outcore, g_outcore);
    cudaGetSymbolAddress((void**)&wt,      g_wt);
    float* wt_val  = wt;
    float* wt_off  = wt + 65536;
    float* wt_attn = wt + 131072;
    float* wt_out  = wt + 196608;

    const size_t smem = 4 * STAGE_F * sizeof(float);   // 73728 B
    cudaFuncSetAttribute((const void*)gemm_mma,
        cudaFuncAttributeMaxDynamicSharedMemorySize, (int)smem);

    const dim3 tb(32, 8);
    transpose_w<<<dim3(8, 8), tb>>>(W_val,  wt_val,  256, 256);
    transpose_w<<<dim3(8, 8), tb>>>(W_off,  wt_off,  256, 256);
    transpose_w<<<dim3(4, 8), tb>>>(W_attn, wt_attn, 256, 128);
    transpose_w<<<dim3(8, 8), tb>>>(W_out,  wt_out,  256, 256);

    const int MT = NQ / 128;   // 680

    gemm_mma<<<dim3(MT, 2), 256, smem>>>(input,   wt_val,  b_val,  value,        256);
    gemm_mma<<<dim3(MT, 2), 256, smem>>>(query,   wt_off,  b_off,  offattn,      384);
    gemm_mma<<<dim3(MT, 1), 256, smem>>>(query,   wt_attn, b_attn, offattn + 256, 384);

    msda_sample2<<<NQ, 128>>>(value, offattn, refpts, spatial, lstart, outcore);

    gemm_mma<<<dim3(MT, 2), 256, smem>>>(outcore, wt_out,  b_out,  out,          256);
}

// round 4
// speedup vs baseline: 6.6624x; 1.1332x over previous
#include <cuda_runtime.h>
#include <cuda_fp16.h>
#include <cstdint>
#include <math.h>

#define B_SZ   4
#define LEN_Q  21760
#define LEN_IN 21760
#define NQ     (B_SZ * LEN_Q)     // 87040
#define DM     256

// Scratch (allocation-free rule: __device__ globals)
__device__ __half g_value[(size_t)NQ * DM];     // [B, Lin, 8, 32] fp16
__device__ float  g_offattn[(size_t)NQ * 384];  // [B*Lq, 256 off | 128 attn]
__device__ float  g_outcore[(size_t)NQ * DM];   // [B*Lq, 256]
__device__ float  g_wt[256*256 + 384*256 + 256*256]; // wt_val | wt_offattn | wt_out
__device__ float  g_bias_oa[384];               // b_off || b_attn

// ---------------------------------------------------------------------------
// helpers
// ---------------------------------------------------------------------------
__device__ __forceinline__ uint32_t smem_u32(const void* p) {
    uint32_t a;
    asm("{ .reg .u64 t; cvta.to.shared.u64 t, %1; cvt.u32.u64 %0, t; }"
        : "=r"(a) : "l"(p));
    return a;
}
__device__ __forceinline__ void cp16(uint32_t dst, const void* src) {
    asm volatile("cp.async.ca.shared.global [%0], [%1], 16;"
                 :: "r"(dst), "l"(src) : "memory");
}
#define CP_COMMIT() asm volatile("cp.async.commit_group;" ::: "memory")
#define CP_WAIT(n)  asm volatile("cp.async.wait_group %0;" :: "n"(n) : "memory")

__device__ __forceinline__ uint32_t lds_tf32(uint32_t addr) {
    float v; uint32_t r;
    asm volatile("ld.shared.f32 %0, [%1];" : "=f"(v) : "r"(addr));
    asm("cvt.rna.tf32.f32 %0, %1;" : "=r"(r) : "f"(v));
    return r;
}
__device__ __forceinline__ void mma_tf32(float* c, const uint32_t* a, const uint32_t* b) {
    asm volatile(
        "mma.sync.aligned.m16n8k8.row.col.f32.tf32.tf32.f32 "
        "{%0,%1,%2,%3}, {%4,%5,%6,%7}, {%8,%9}, {%0,%1,%2,%3};"
        : "+f"(c[0]), "+f"(c[1]), "+f"(c[2]), "+f"(c[3])
        : "r"(a[0]), "r"(a[1]), "r"(a[2]), "r"(a[3]), "r"(b[0]), "r"(b[1]));
}

// ---------------------------------------------------------------------------
// Fused weight transpose + bias pack.
// z=0: wt_val[256,256] <- W_val[256,256]^T
// z=1: wt_offattn[384,256] <- [W_off | W_attn]^T   (+ bias pack in block 0,0)
// z=2: wt_out[256,256] <- W_out[256,256]^T
// grid (12, 8, 3), block (32, 8); x-guard for z!=1.
// ---------------------------------------------------------------------------
__global__ void transpose_all(const float* __restrict__ Wv,
                              const float* __restrict__ Wo,
                              const float* __restrict__ Wa,
                              const float* __restrict__ Wu,
                              const float* __restrict__ b_off,
                              const float* __restrict__ b_attn,
                              float* __restrict__ wt,
                              float* __restrict__ bias_oa)
{
    const int z = blockIdx.z;
    const int bx = blockIdx.x, by = blockIdx.y;
    const int tx = threadIdx.x, ty = threadIdx.y;
    const int tid = ty * 32 + tx;

    if (z == 1 && bx == 0 && by == 0) {
        if (tid < 256) bias_oa[tid] = b_off[tid];
        if (tid < 128) bias_oa[256 + tid] = b_attn[tid];
    }
    if (z != 1 && bx >= 8) return;
    if (z == 1 && bx >= 12) return;

    const int n0 = bx << 5, k0 = by << 5;
    const float* src;
    float* dst;
    int N, ncol0;
    if (z == 0)      { src = Wv; dst = wt;                 N = 256; ncol0 = n0; }
    else if (z == 2) { src = Wu; dst = wt + 65536 + 98304; N = 256; ncol0 = n0; }
    else if (n0 < 256) { src = Wo; dst = wt + 65536;       N = 256; ncol0 = n0; }
    else             { src = Wa; dst = wt + 65536;         N = 128; ncol0 = n0 - 256; }

    __shared__ float t[32][33];
    #pragma unroll
    for (int i = 0; i < 4; ++i)
        t[ty + 8 * i][tx] = src[(size_t)(k0 + ty + 8 * i) * N + ncol0 + tx];
    __syncthreads();
    #pragma unroll
    for (int i = 0; i < 4; ++i)
        dst[(size_t)(n0 + ty + 8 * i) * 256 + k0 + tx] = t[tx][ty + 8 * i];
}

// ---------------------------------------------------------------------------
// mma.sync tf32 GEMM: C tile = A[M,256] @ Bt[N,256]^T + bias
// CTA tile 128x128, 8 warps (2M x 4N), warp tile 64x32, k-chunks of 32,
// cp.async double-buffered. Smem pitch 36 floats -> conflict-free LDS.
// HALF_OUT: write __half instead of float.
// ---------------------------------------------------------------------------
#define PITCH 36
#define STAGE_F (128 * PITCH)

template<bool HALF_OUT>
__global__ __launch_bounds__(256, 2)
void gemm_mma(const float* __restrict__ A, const float* __restrict__ Bt,
              const float* __restrict__ bias, void* __restrict__ Cv, int ldc)
{
    extern __shared__ float sm[];
    const int tid = threadIdx.x, wid = tid >> 5, lane = tid & 31;
    const int bm = blockIdx.x << 7;
    const int bn = blockIdx.y << 7;
    const int wm = (wid >> 2) << 6;
    const int wn = (wid & 3) << 5;

    const float* Ag = A  + (size_t)bm * 256;
    const float* Bg = Bt + (size_t)bn * 256;
    const uint32_t sb = smem_u32(sm);

    auto load = [&](int c, int s) {
        const int k0 = c * 32;
        const uint32_t sa  = sb + (uint32_t)(s * 2) * STAGE_F * 4;
        const uint32_t sbB = sb + (uint32_t)(s * 2 + 1) * STAGE_F * 4;
        #pragma unroll
        for (int i = 0; i < 4; ++i) {
            int f = tid + i * 256;
            int row = f >> 3, c4 = (f & 7) * 4;
            cp16(sa  + (uint32_t)(row * PITCH + c4) * 4, Ag + (size_t)row * 256 + k0 + c4);
            cp16(sbB + (uint32_t)(row * PITCH + c4) * 4, Bg + (size_t)row * 256 + k0 + c4);
        }
        CP_COMMIT();
    };

    float acc[4][4][4] = {};

    load(0, 0);
    load(1, 1);

    const int gm = lane >> 2, gk = lane & 3;

    #pragma unroll
    for (int ch = 0; ch < 8; ++ch) {
        const int s = ch & 1;
        if (ch == 7) CP_WAIT(0); else CP_WAIT(1);
        __syncthreads();

        const uint32_t sa  = sb + (uint32_t)(s * 2) * STAGE_F * 4;
        const uint32_t sbB = sb + (uint32_t)(s * 2 + 1) * STAGE_F * 4;

        #pragma unroll
        for (int kk = 0; kk < 4; ++kk) {
            const int kb = kk * 8 + gk;
            uint32_t afr[4][4], bfr[4][2];
            #pragma unroll
            for (int mt = 0; mt < 4; ++mt) {
                const uint32_t base = sa + (uint32_t)((wm + mt * 16 + gm) * PITCH + kb) * 4;
                afr[mt][0] = lds_tf32(base);
                afr[mt][1] = lds_tf32(base + 8 * PITCH * 4);
                afr[mt][2] = lds_tf32(base + 16);
                afr[mt][3] = lds_tf32(base + 8 * PITCH * 4 + 16);
            }
            #pragma unroll
            for (int nt = 0; nt < 4; ++nt) {
                const uint32_t base = sbB + (uint32_t)((wn + nt * 8 + gm) * PITCH + kb) * 4;
                bfr[nt][0] = lds_tf32(base);
                bfr[nt][1] = lds_tf32(base + 16);
            }
            #pragma unroll
            for (int mt = 0; mt < 4; ++mt)
                #pragma unroll
                for (int nt = 0; nt < 4; ++nt)
                    mma_tf32(acc[mt][nt], afr[mt], bfr[nt]);
        }
        __syncthreads();
        if (ch + 2 < 8) load(ch + 2, s);
    }

    const int gn2 = (lane & 3) * 2;
    #pragma unroll
    for (int nt = 0; nt < 4; ++nt) {
        const int col = bn + wn + nt * 8 + gn2;
        const float b0 = bias[col], b1 = bias[col + 1];
        #pragma unroll
        for (int mt = 0; mt < 4; ++mt) {
            const int r0 = bm + wm + mt * 16 + gm;
            if (HALF_OUT) {
                __half* C = (__half*)Cv;
                *(__half2*)(C + (size_t)r0 * ldc + col) =
                    __floats2half2_rn(acc[mt][nt][0] + b0, acc[mt][nt][1] + b1);
                *(__half2*)(C + (size_t)(r0 + 8) * ldc + col) =
                    __floats2half2_rn(acc[mt][nt][2] + b0, acc[mt][nt][3] + b1);
            } else {
                float* C = (float*)Cv;
                float2 o0 = { acc[mt][nt][0] + b0, acc[mt][nt][1] + b1 };
                float2 o1 = { acc[mt][nt][2] + b0, acc[mt][nt][3] + b1 };
                *(float2*)(C + (size_t)r0 * ldc + col) = o0;
                *(float2*)(C + (size_t)(r0 + 8) * ldc + col) = o1;
            }
        }
    }
}

// ---------------------------------------------------------------------------
// Deformable sampling: block = 1 query (128 threads, 4 warps).
// Warp w serves heads 2w, 2w+1; lane = (head-half, half2-of-channels).
// Setup: 32 lanes compute the warp's 32 (head,sample) parameter sets
// (softmax + bilinear weights + clamped corner indices) -> smem.
// Gather: per sample 2x LDS.128 + 4x LDG.32(half2) + cvt + 8 FFMA.
// ---------------------------------------------------------------------------
__global__ __launch_bounds__(128)
void msda_sample2(const __half* __restrict__ value,   // [B, Lin, 8, 32] fp16
                  const float* __restrict__ offattn,  // [B*Lq, 384]
                  const float* __restrict__ refpts,   // [B, Lq, 4, 2]
                  const int*   __restrict__ spatial,  // [4, 2]
                  const int*   __restrict__ lstart,   // [4]
                  float* __restrict__ outcore)        // [B*Lq, 256]
{
    const int qg  = blockIdx.x;
    const int b   = qg / LEN_Q;
    const int tid = threadIdx.x, wid = tid >> 5, lane = tid & 31;

    __shared__ float s_ref[8];
    __shared__ int   s_H[4], s_W[4], s_S[4];
    __shared__ __align__(16) float s_par[8][17][8];   // [head][sample][4 idx | 4 w]

    if (tid < 4) {
        s_H[tid] = spatial[2 * tid];
        s_W[tid] = spatial[2 * tid + 1];
        s_S[tid] = lstart[tid];
    }
    if (tid < 8) s_ref[tid] = refpts[(size_t)qg * 8 + tid];
    __syncthreads();

    const float* oa = offattn + (size_t)qg * 384;

    {
        const int hh = lane >> 4, s = lane & 15;
        const int head = 2 * wid + hh, l = s >> 2;

        float logit = oa[256 + head * 16 + s];
        float mx = logit;
        #pragma unroll
        for (int d = 8; d; d >>= 1) mx = fmaxf(mx, __shfl_xor_sync(0xffffffffu, mx, d));
        float e = expf(logit - mx);
        float sum = e;
        #pragma unroll
        for (int d = 8; d; d >>= 1) sum += __shfl_xor_sync(0xffffffffu, sum, d);
        const float aw = e / sum;

        const int H = s_H[l], W = s_W[l], st = s_S[l];
        const float Wf = (float)W, Hf = (float)H;
        const float ox = oa[head * 32 + 2 * s];
        const float oy = oa[head * 32 + 2 * s + 1];
        const float lx = s_ref[2 * l]     + ox / Wf;
        const float ly = s_ref[2 * l + 1] + oy / Hf;
        const float x = lx * Wf - 0.5f;
        const float y = ly * Hf - 0.5f;
        const float x0f = floorf(x), y0f = floorf(y);
        const float fx = x - x0f, fy = y - y0f;
        const int x0 = (int)x0f, y0 = (int)y0f;
        const int x1 = x0 + 1, y1 = y0 + 1;

        const float vx0 = (x0 >= 0 && x0 < W) ? 1.f : 0.f;
        const float vx1 = (x1 >= 0 && x1 < W) ? 1.f : 0.f;
        const float vy0 = (y0 >= 0 && y0 < H) ? 1.f : 0.f;
        const float vy1 = (y1 >= 0 && y1 < H) ? 1.f : 0.f;
        const int cx0 = min(max(x0, 0), W - 1), cx1 = min(max(x1, 0), W - 1);
        const int cy0 = min(max(y0, 0), H - 1), cy1 = min(max(y1, 0), H - 1);

        float* p = s_par[head][s];
        p[0] = __int_as_float(st + cy0 * W + cx0);
        p[1] = __int_as_float(st + cy0 * W + cx1);
        p[2] = __int_as_float(st + cy1 * W + cx0);
        p[3] = __int_as_float(st + cy1 * W + cx1);
        p[4] = aw * (1.f - fx) * (1.f - fy) * vx0 * vy0;
        p[5] = aw * fx * (1.f - fy) * vx1 * vy0;
        p[6] = aw * (1.f - fx) * fy * vx0 * vy1;
        p[7] = aw * fx * fy * vx1 * vy1;
    }
    __syncwarp();

    const int hh = lane >> 4, head = 2 * wid + hh, ch2 = lane & 15;
    const __half2* vb =
        (const __half2*)(value + (size_t)b * LEN_IN * 256 + head * 32) + ch2;

    float ax = 0.f, ay = 0.f;
    #pragma unroll
    for (int s = 0; s < 16; ++s) {
        const float4 pi = *(const float4*)&s_par[head][s][0];
        const float4 pw = *(const float4*)&s_par[head][s][4];
        const float2 v0 = __half22float2(vb[(size_t)__float_as_int(pi.x) * 128]);
        const float2 v1 = __half22float2(vb[(size_t)__float_as_int(pi.y) * 128]);
        const float2 v2 = __half22float2(vb[(size_t)__float_as_int(pi.z) * 128]);
        const float2 v3 = __half22float2(vb[(size_t)__float_as_int(pi.w) * 128]);
        ax += pw.x * v0.x + pw.y * v1.x + pw.z * v2.x + pw.w * v3.x;
        ay += pw.x * v0.y + pw.y * v1.y + pw.z * v2.y + pw.w * v3.y;
    }
    float2 o = { ax, ay };
    *(float2*)(outcore + (size_t)qg * 256 + head * 32 + 2 * ch2) = o;
}

// ---------------------------------------------------------------------------
extern "C" void kernel_launch(void* const* d_in, const int* in_sizes, int n_in,
                              void* d_out, int out_size)
{
    const float* query   = (const float*)d_in[0];
    const float* refpts  = (const float*)d_in[1];
    const float* input   = (const float*)d_in[2];
    const int*   spatial = (const int*)  d_in[3];
    const int*   lstart  = (const int*)  d_in[4];
    const float* W_off   = (const float*)d_in[5];
    const float* b_off   = (const float*)d_in[6];
    const float* W_attn  = (const float*)d_in[7];
    const float* b_attn  = (const float*)d_in[8];
    const float* W_val   = (const float*)d_in[9];
    const float* b_val   = (const float*)d_in[10];
    const float* W_out   = (const float*)d_in[11];
    const float* b_out   = (const float*)d_in[12];
    float* out = (float*)d_out;

    __half* value;
    float *offattn, *outcore, *wt, *bias_oa;
    cudaGetSymbolAddress((void**)&value,   g_value);
    cudaGetSymbolAddress((void**)&offattn, g_offattn);
    cudaGetSymbolAddress((void**)&outcore, g_outcore);
    cudaGetSymbolAddress((void**)&wt,      g_wt);
    cudaGetSymbolAddress((void**)&bias_oa, g_bias_oa);
    float* wt_val     = wt;
    float* wt_offattn = wt + 65536;
    float* wt_out     = wt + 65536 + 98304;

    const size_t smem = 4 * STAGE_F * sizeof(float);   // 73728 B
    cudaFuncSetAttribute((const void*)gemm_mma<false>,
        cudaFuncAttributeMaxDynamicSharedMemorySize, (int)smem);
    cudaFuncSetAttribute((const void*)gemm_mma<true>,
        cudaFuncAttributeMaxDynamicSharedMemorySize, (int)smem);

    transpose_all<<<dim3(12, 8, 3), dim3(32, 8)>>>(
        W_val, W_off, W_attn, W_out, b_off, b_attn, wt, bias_oa);

    const int MT = NQ / 128;   // 680

    // value projection -> fp16
    gemm_mma<true><<<dim3(MT, 2), 256, smem>>>(input, wt_val, b_val, value, 256);
    // fused offsets + attn logits (N = 384)
    gemm_mma<false><<<dim3(MT, 3), 256, smem>>>(query, wt_offattn, bias_oa, offattn, 384);

    msda_sample2<<<NQ, 128>>>(value, offattn, refpts, spatial, lstart, outcore);

    gemm_mma<false><<<dim3(MT, 2), 256, smem>>>(outcore, wt_out, b_out, out, 256);
}

// round 7
// speedup vs baseline: 6.9891x; 1.0490x over previous
#include <cuda_runtime.h>
#include <cuda_fp16.h>
#include <cstdint>
#include <math.h>

#define B_SZ   4
#define LEN_Q  21760
#define LEN_IN 21760
#define NQ     (B_SZ * LEN_Q)     // 87040
#define DM     256

// Scratch (allocation-free rule: __device__ globals)
__device__ __half g_value[(size_t)NQ * DM];     // [B, Lin, 8, 32] fp16
__device__ float  g_offattn[(size_t)NQ * 384];  // [B*Lq, 256 off | 128 attn]
__device__ float  g_outcore[(size_t)NQ * DM];   // [B*Lq, 256]
__device__ __half g_wt16[256*256 + 384*256 + 256*256]; // wt_val | wt_offattn | wt_out
__device__ float  g_bias_oa[384];               // b_off || b_attn

// ---------------------------------------------------------------------------
// helpers
// ---------------------------------------------------------------------------
__device__ __forceinline__ uint32_t smem_u32(const void* p) {
    uint32_t a;
    asm("{ .reg .u64 t; cvta.to.shared.u64 t, %1; cvt.u32.u64 %0, t; }"
        : "=r"(a) : "l"(p));
    return a;
}
__device__ __forceinline__ uint32_t h2_bits(__half2 h) {
    union { __half2 h; uint32_t u; } cvt;
    cvt.h = h;
    return cvt.u;
}
__device__ __forceinline__ void cp16(uint32_t dst, const void* src) {
    asm volatile("cp.async.ca.shared.global [%0], [%1], 16;"
                 :: "r"(dst), "l"(src) : "memory");
}
#define CP_COMMIT() asm volatile("cp.async.commit_group;" ::: "memory")
#define CP_WAIT(n)  asm volatile("cp.async.wait_group %0;" :: "n"(n) : "memory")

__device__ __forceinline__ void ldm4(uint32_t* r, uint32_t addr) {
    asm volatile("ldmatrix.sync.aligned.m8n8.x4.shared.b16 {%0,%1,%2,%3}, [%4];"
        : "=r"(r[0]), "=r"(r[1]), "=r"(r[2]), "=r"(r[3]) : "r"(addr));
}
__device__ __forceinline__ void mma_f16(float* c, const uint32_t* a, const uint32_t* b) {
    asm volatile(
        "mma.sync.aligned.m16n8k16.row.col.f32.f16.f16.f32 "
        "{%0,%1,%2,%3}, {%4,%5,%6,%7}, {%8,%9}, {%0,%1,%2,%3};"
        : "+f"(c[0]), "+f"(c[1]), "+f"(c[2]), "+f"(c[3])
        : "r"(a[0]), "r"(a[1]), "r"(a[2]), "r"(a[3]), "r"(b[0]), "r"(b[1]));
}
// swizzled offset within a [128 rows x 32 halves] tile (64B rows, 16B units
// XOR-permuted by (row>>1)&3 -> ldmatrix phases conflict-free)
__device__ __forceinline__ uint32_t swz(int row, int kh) {
    return (uint32_t)(row * 64 + ((((kh >> 3) ^ ((row >> 1) & 3))) << 4) + (kh & 7) * 2);
}

// ---------------------------------------------------------------------------
// Fused weight transpose (fp32 -> fp16, [K,N] -> [N,K]) + bias pack.
// z=0: wt_val, z=1: wt_offattn (+bias pack), z=2: wt_out
// ---------------------------------------------------------------------------
__global__ void transpose_all(const float* __restrict__ Wv,
                              const float* __restrict__ Wo,
                              const float* __restrict__ Wa,
                              const float* __restrict__ Wu,
                              const float* __restrict__ b_off,
                              const float* __restrict__ b_attn,
                              __half* __restrict__ wt,
                              float* __restrict__ bias_oa)
{
    const int z = blockIdx.z;
    const int bx = blockIdx.x, by = blockIdx.y;
    const int tx = threadIdx.x, ty = threadIdx.y;
    const int tid = ty * 32 + tx;

    if (z == 1 && bx == 0 && by == 0) {
        if (tid < 256) bias_oa[tid] = b_off[tid];
        if (tid < 128) bias_oa[256 + tid] = b_attn[tid];
    }
    if (z != 1 && bx >= 8) return;
    if (z == 1 && bx >= 12) return;

    const int n0 = bx << 5, k0 = by << 5;
    const float* src;
    __half* dst;
    int N, ncol0;
    if (z == 0)        { src = Wv; dst = wt;                 N = 256; ncol0 = n0; }
    else if (z == 2)   { src = Wu; dst = wt + 65536 + 98304; N = 256; ncol0 = n0; }
    else if (n0 < 256) { src = Wo; dst = wt + 65536;         N = 256; ncol0 = n0; }
    else               { src = Wa; dst = wt + 65536;         N = 128; ncol0 = n0 - 256; }

    __shared__ float t[32][33];
    #pragma unroll
    for (int i = 0; i < 4; ++i)
        t[ty + 8 * i][tx] = src[(size_t)(k0 + ty + 8 * i) * N + ncol0 + tx];
    __syncthreads();
    #pragma unroll
    for (int i = 0; i < 4; ++i)
        dst[(size_t)(n0 + ty + 8 * i) * 256 + k0 + tx] = __float2half(t[tx][ty + 8 * i]);
}

// ---------------------------------------------------------------------------
// fp16 mma.sync GEMM: C tile = A[M,256](fp32) @ Bt[N,256](fp16)^T + bias(fp32)
// CTA 128x128, 8 warps (2M x 4N), warp tile 64x32, k-chunks of 32.
// B via cp.async (double buffer); A via LDG->cvt->STS, reg double-buffered.
// ---------------------------------------------------------------------------
#define STAGE_B 16384   // bytes per stage: A 8KB + B 8KB

template<bool HALF_OUT>
__global__ __launch_bounds__(256, 2)
void gemm_f16(const float* __restrict__ A, const __half* __restrict__ Bt,
              const float* __restrict__ bias, void* __restrict__ Cv, int ldc)
{
    extern __shared__ char smc[];
    const uint32_t sb = smem_u32(smc);
    const int tid = threadIdx.x, wid = tid >> 5, lane = tid & 31;
    const int bm = blockIdx.x << 7;
    const int bn = blockIdx.y << 7;
    const int wm = (wid >> 2) << 6;
    const int wn = (wid & 3) << 5;

    const float* Ag = A + (size_t)bm * 256;
    const __half* Bg = Bt + (size_t)bn * 256;

    const int arow = tid >> 1, ahalf = tid & 1;

    auto ldgA = [&](int c, float4* v) {
        const float* p = Ag + (size_t)arow * 256 + c * 32 + ahalf * 16;
        #pragma unroll
        for (int j = 0; j < 4; ++j) v[j] = *(const float4*)(p + j * 4);
    };
    auto stsA = [&](const float4* v, uint32_t saA) {
        #pragma unroll
        for (int j = 0; j < 4; ++j) {
            const int kh = ahalf * 16 + j * 4;
            uint32_t h01 = h2_bits(__floats2half2_rn(v[j].x, v[j].y));
            uint32_t h23 = h2_bits(__floats2half2_rn(v[j].z, v[j].w));
            asm volatile("st.shared.v2.b32 [%0], {%1, %2};"
                :: "r"(saA + swz(arow, kh)), "r"(h01), "r"(h23) : "memory");
        }
    };
    auto cpB = [&](int c, uint32_t sB) {
        #pragma unroll
        for (int j = 0; j < 2; ++j) {
            const int kh = ahalf * 16 + j * 8;
            cp16(sB + swz(arow, kh), Bg + (size_t)arow * 256 + c * 32 + kh);
        }
        CP_COMMIT();
    };

    // per-warp ldmatrix lane offsets (ks=0); ks=1 -> XOR 32
    uint32_t aoff[4], boff[2];
    {
        const int ar = (lane & 15), akh = (lane >> 4) * 8;
        #pragma unroll
        for (int mt = 0; mt < 4; ++mt) aoff[mt] = swz(wm + mt * 16 + ar, akh);
        const int br0 = (lane & 7) + ((lane >> 4) << 3), bkh = lane & 8;
        #pragma unroll
        for (int n2 = 0; n2 < 2; ++n2) boff[n2] = swz(wn + n2 * 16 + br0, bkh);
    }

    float acc[4][4][4] = {};
    float4 ra[4];

    // prologue
    cpB(0, sb + 8192);
    cpB(1, sb + STAGE_B + 8192);
    ldgA(0, ra); stsA(ra, sb);
    ldgA(1, ra);

    #pragma unroll
    for (int c = 0; c < 8; ++c) {
        const int s = c & 1;
        const uint32_t st = sb + (uint32_t)s * STAGE_B;
        if (c == 7) CP_WAIT(0); else CP_WAIT(1);
        __syncthreads();
        if (c + 1 < 8) stsA(ra, sb + (uint32_t)(s ^ 1) * STAGE_B);

        #pragma unroll
        for (int ks = 0; ks < 2; ++ks) {
            const uint32_t xo = ks * 32;
            uint32_t afr[4][4], bfr[2][4];
            #pragma unroll
            for (int mt = 0; mt < 4; ++mt) ldm4(afr[mt], st + (aoff[mt] ^ xo));
            #pragma unroll
            for (int n2 = 0; n2 < 2; ++n2) ldm4(bfr[n2], st + 8192 + (boff[n2] ^ xo));
            #pragma unroll
            for (int mt = 0; mt < 4; ++mt)
                #pragma unroll
                for (int nt = 0; nt < 4; ++nt)
                    mma_f16(acc[mt][nt], afr[mt], &bfr[nt >> 1][(nt & 1) * 2]);
        }
        __syncthreads();
        if (c + 2 < 8) { cpB(c + 2, st + 8192); ldgA(c + 2, ra); }
    }

    // epilogue
    const int gm = lane >> 2, gn2 = (lane & 3) * 2;
    #pragma unroll
    for (int nt = 0; nt < 4; ++nt) {
        const int col = bn + wn + nt * 8 + gn2;
        const float b0 = bias[col], b1 = bias[col + 1];
        #pragma unroll
        for (int mt = 0; mt < 4; ++mt) {
            const int r0 = bm + wm + mt * 16 + gm;
            if (HALF_OUT) {
                __half* C = (__half*)Cv;
                *(__half2*)(C + (size_t)r0 * ldc + col) =
                    __floats2half2_rn(acc[mt][nt][0] + b0, acc[mt][nt][1] + b1);
                *(__half2*)(C + (size_t)(r0 + 8) * ldc + col) =
                    __floats2half2_rn(acc[mt][nt][2] + b0, acc[mt][nt][3] + b1);
            } else {
                float* C = (float*)Cv;
                float2 o0 = { acc[mt][nt][0] + b0, acc[mt][nt][1] + b1 };
                float2 o1 = { acc[mt][nt][2] + b0, acc[mt][nt][3] + b1 };
                *(float2*)(C + (size_t)r0 * ldc + col) = o0;
                *(float2*)(C + (size_t)(r0 + 8) * ldc + col) = o1;
            }
        }
    }
}

// ---------------------------------------------------------------------------
// Deformable sampling (unchanged from R4): block = 1 query (128 thr, 4 warps).
// ---------------------------------------------------------------------------
__global__ __launch_bounds__(128)
void msda_sample2(const __half* __restrict__ value,   // [B, Lin, 8, 32] fp16
                  const float* __restrict__ offattn,  // [B*Lq, 384]
                  const float* __restrict__ refpts,   // [B, Lq, 4, 2]
                  const int*   __restrict__ spatial,  // [4, 2]
                  const int*   __restrict__ lstart,   // [4]
                  float* __restrict__ outcore)        // [B*Lq, 256]
{
    const int qg  = blockIdx.x;
    const int b   = qg / LEN_Q;
    const int tid = threadIdx.x, wid = tid >> 5, lane = tid & 31;

    __shared__ float s_ref[8];
    __shared__ int   s_H[4], s_W[4], s_S[4];
    __shared__ __align__(16) float s_par[8][17][8];   // [head][sample][4 idx | 4 w]

    if (tid < 4) {
        s_H[tid] = spatial[2 * tid];
        s_W[tid] = spatial[2 * tid + 1];
        s_S[tid] = lstart[tid];
    }
    if (tid < 8) s_ref[tid] = refpts[(size_t)qg * 8 + tid];
    __syncthreads();

    const float* oa = offattn + (size_t)qg * 384;

    {
        const int hh = lane >> 4, s = lane & 15;
        const int head = 2 * wid + hh, l = s >> 2;

        float logit = oa[256 + head * 16 + s];
        float mx = logit;
        #pragma unroll
        for (int d = 8; d; d >>= 1) mx = fmaxf(mx, __shfl_xor_sync(0xffffffffu, mx, d));
        float e = expf(logit - mx);
        float sum = e;
        #pragma unroll
        for (int d = 8; d; d >>= 1) sum += __shfl_xor_sync(0xffffffffu, sum, d);
        const float aw = e / sum;

        const int H = s_H[l], W = s_W[l], st = s_S[l];
        const float Wf = (float)W, Hf = (float)H;
        const float ox = oa[head * 32 + 2 * s];
        const float oy = oa[head * 32 + 2 * s + 1];
        const float lx = s_ref[2 * l]     + ox / Wf;
        const float ly = s_ref[2 * l + 1] + oy / Hf;
        const float x = lx * Wf - 0.5f;
        const float y = ly * Hf - 0.5f;
        const float x0f = floorf(x), y0f = floorf(y);
        const float fx = x - x0f, fy = y - y0f;
        const int x0 = (int)x0f, y0 = (int)y0f;
        const int x1 = x0 + 1, y1 = y0 + 1;

        const float vx0 = (x0 >= 0 && x0 < W) ? 1.f : 0.f;
        const float vx1 = (x1 >= 0 && x1 < W) ? 1.f : 0.f;
        const float vy0 = (y0 >= 0 && y0 < H) ? 1.f : 0.f;
        const float vy1 = (y1 >= 0 && y1 < H) ? 1.f : 0.f;
        const int cx0 = min(max(x0, 0), W - 1), cx1 = min(max(x1, 0), W - 1);
        const int cy0 = min(max(y0, 0), H - 1), cy1 = min(max(y1, 0), H - 1);

        float* p = s_par[head][s];
        p[0] = __int_as_float(st + cy0 * W + cx0);
        p[1] = __int_as_float(st + cy0 * W + cx1);
        p[2] = __int_as_float(st + cy1 * W + cx0);
        p[3] = __int_as_float(st + cy1 * W + cx1);
        p[4] = aw * (1.f - fx) * (1.f - fy) * vx0 * vy0;
        p[5] = aw * fx * (1.f - fy) * vx1 * vy0;
        p[6] = aw * (1.f - fx) * fy * vx0 * vy1;
        p[7] = aw * fx * fy * vx1 * vy1;
    }
    __syncwarp();

    const int hh = lane >> 4, head = 2 * wid + hh, ch2 = lane & 15;
    const __half2* vb =
        (const __half2*)(value + (size_t)b * LEN_IN * 256 + head * 32) + ch2;

    float ax = 0.f, ay = 0.f;
    #pragma unroll
    for (int s = 0; s < 16; ++s) {
        const float4 pi = *(const float4*)&s_par[head][s][0];
        const float4 pw = *(const float4*)&s_par[head][s][4];
        const float2 v0 = __half22float2(vb[(size_t)__float_as_int(pi.x) * 128]);
        const float2 v1 = __half22float2(vb[(size_t)__float_as_int(pi.y) * 128]);
        const float2 v2 = __half22float2(vb[(size_t)__float_as_int(pi.z) * 128]);
        const float2 v3 = __half22float2(vb[(size_t)__float_as_int(pi.w) * 128]);
        ax += pw.x * v0.x + pw.y * v1.x + pw.z * v2.x + pw.w * v3.x;
        ay += pw.x * v0.y + pw.y * v1.y + pw.z * v2.y + pw.w * v3.y;
    }
    float2 o = { ax, ay };
    *(float2*)(outcore + (size_t)qg * 256 + head * 32 + 2 * ch2) = o;
}

// ---------------------------------------------------------------------------
extern "C" void kernel_launch(void* const* d_in, const int* in_sizes, int n_in,
                              void* d_out, int out_size)
{
    const float* query   = (const float*)d_in[0];
    const float* refpts  = (const float*)d_in[1];
    const float* input   = (const float*)d_in[2];
    const int*   spatial = (const int*)  d_in[3];
    const int*   lstart  = (const int*)  d_in[4];
    const float* W_off   = (const float*)d_in[5];
    const float* b_off   = (const float*)d_in[6];
    const float* W_attn  = (const float*)d_in[7];
    const float* b_attn  = (const float*)d_in[8];
    const float* W_val   = (const float*)d_in[9];
    const float* b_val   = (const float*)d_in[10];
    const float* W_out   = (const float*)d_in[11];
    const float* b_out   = (const float*)d_in[12];
    float* out = (float*)d_out;

    __half *value, *wt;
    float *offattn, *outcore, *bias_oa;
    cudaGetSymbolAddress((void**)&value,   g_value);
    cudaGetSymbolAddress((void**)&offattn, g_offattn);
    cudaGetSymbolAddress((void**)&outcore, g_outcore);
    cudaGetSymbolAddress((void**)&wt,      g_wt16);
    cudaGetSymbolAddress((void**)&bias_oa, g_bias_oa);
    __half* wt_val     = wt;
    __half* wt_offattn = wt + 65536;
    __half* wt_out     = wt + 65536 + 98304;

    const size_t smem = 2 * STAGE_B;   // 32768 B
    cudaFuncSetAttribute((const void*)gemm_f16<false>,
        cudaFuncAttributeMaxDynamicSharedMemorySize, (int)smem);
    cudaFuncSetAttribute((const void*)gemm_f16<true>,
        cudaFuncAttributeMaxDynamicSharedMemorySize, (int)smem);

    transpose_all<<<dim3(12, 8, 3), dim3(32, 8)>>>(
        W_val, W_off, W_attn, W_out, b_off, b_attn, wt, bias_oa);

    const int MT = NQ / 128;   // 680

    // value projection -> fp16
    gemm_f16<true><<<dim3(MT, 2), 256, smem>>>(input, wt_val, b_val, value, 256);
    // fused offsets + attn logits (N = 384)
    gemm_f16<false><<<dim3(MT, 3), 256, smem>>>(query, wt_offattn, bias_oa, offattn, 384);

    msda_sample2<<<NQ, 128>>>(value, offattn, refpts, spatial, lstart, outcore);

    gemm_f16<false><<<dim3(MT, 2), 256, smem>>>(outcore, wt_out, b_out, out, 256);
}

// round 9
// speedup vs baseline: 7.2464x; 1.0368x over previous
#include <cuda_runtime.h>
#include <cuda_fp16.h>
#include <cstdint>
#include <math.h>

#define B_SZ   4
#define LEN_Q  21760
#define LEN_IN 21760
#define NQ     (B_SZ * LEN_Q)     // 87040
#define DM     256

// Scratch (allocation-free rule: __device__ globals)
__device__ __half g_value[(size_t)NQ * DM];     // [B, Lin, 8, 32] fp16
__device__ float  g_offattn[(size_t)NQ * 384];  // [B*Lq, 256 off | 128 attn]
__device__ float  g_outcore[(size_t)NQ * DM];   // [B*Lq, 256]
__device__ __half g_wt16[256*256 + 384*256 + 256*256]; // wt_val | wt_offattn | wt_out
__device__ float  g_bias_oa[384];               // b_off || b_attn

// ---------------------------------------------------------------------------
// helpers
// ---------------------------------------------------------------------------
__device__ __forceinline__ uint32_t smem_u32(const void* p) {
    uint32_t a;
    asm("{ .reg .u64 t; cvta.to.shared.u64 t, %1; cvt.u32.u64 %0, t; }"
        : "=r"(a) : "l"(p));
    return a;
}
__device__ __forceinline__ uint32_t h2_bits(__half2 h) {
    union { __half2 h; uint32_t u; } cvt;
    cvt.h = h;
    return cvt.u;
}
__device__ __forceinline__ void cp16(uint32_t dst, const void* src) {
    asm volatile("cp.async.ca.shared.global [%0], [%1], 16;"
                 :: "r"(dst), "l"(src) : "memory");
}
#define CP_COMMIT() asm volatile("cp.async.commit_group;" ::: "memory")
#define CP_WAIT(n)  asm volatile("cp.async.wait_group %0;" :: "n"(n) : "memory")

__device__ __forceinline__ void ldm4(uint32_t* r, uint32_t addr) {
    asm volatile("ldmatrix.sync.aligned.m8n8.x4.shared.b16 {%0,%1,%2,%3}, [%4];"
        : "=r"(r[0]), "=r"(r[1]), "=r"(r[2]), "=r"(r[3]) : "r"(addr));
}
__device__ __forceinline__ void mma_f16(float* c, const uint32_t* a, const uint32_t* b) {
    asm volatile(
        "mma.sync.aligned.m16n8k16.row.col.f32.f16.f16.f32 "
        "{%0,%1,%2,%3}, {%4,%5,%6,%7}, {%8,%9}, {%0,%1,%2,%3};"
        : "+f"(c[0]), "+f"(c[1]), "+f"(c[2]), "+f"(c[3])
        : "r"(a[0]), "r"(a[1]), "r"(a[2]), "r"(a[3]), "r"(b[0]), "r"(b[1]));
}
// swizzled offset within a [128 rows x 32 halves] tile (64B rows, 16B units
// XOR-permuted by (row>>1)&3 -> ldmatrix phases conflict-free)
__device__ __forceinline__ uint32_t swz(int row, int kh) {
    return (uint32_t)(row * 64 + ((((kh >> 3) ^ ((row >> 1) & 3))) << 4) + (kh & 7) * 2);
}

// ---------------------------------------------------------------------------
// Fused weight transpose (fp32 -> fp16, [K,N] -> [N,K]) + bias pack.
// ---------------------------------------------------------------------------
__global__ void transpose_all(const float* __restrict__ Wv,
                              const float* __restrict__ Wo,
                              const float* __restrict__ Wa,
                              const float* __restrict__ Wu,
                              const float* __restrict__ b_off,
                              const float* __restrict__ b_attn,
                              __half* __restrict__ wt,
                              float* __restrict__ bias_oa)
{
    const int z = blockIdx.z;
    const int bx = blockIdx.x, by = blockIdx.y;
    const int tx = threadIdx.x, ty = threadIdx.y;
    const int tid = ty * 32 + tx;

    if (z == 1 && bx == 0 && by == 0) {
        if (tid < 256) bias_oa[tid] = b_off[tid];
        if (tid < 128) bias_oa[256 + tid] = b_attn[tid];
    }
    if (z != 1 && bx >= 8) return;
    if (z == 1 && bx >= 12) return;

    const int n0 = bx << 5, k0 = by << 5;
    const float* src;
    __half* dst;
    int N, ncol0;
    if (z == 0)        { src = Wv; dst = wt;                 N = 256; ncol0 = n0; }
    else if (z == 2)   { src = Wu; dst = wt + 65536 + 98304; N = 256; ncol0 = n0; }
    else if (n0 < 256) { src = Wo; dst = wt + 65536;         N = 256; ncol0 = n0; }
    else               { src = Wa; dst = wt + 65536;         N = 128; ncol0 = n0 - 256; }

    __shared__ float t[32][33];
    #pragma unroll
    for (int i = 0; i < 4; ++i)
        t[ty + 8 * i][tx] = src[(size_t)(k0 + ty + 8 * i) * N + ncol0 + tx];
    __syncthreads();
    #pragma unroll
    for (int i = 0; i < 4; ++i)
        dst[(size_t)(n0 + ty + 8 * i) * 256 + k0 + tx] = __float2half(t[tx][ty + 8 * i]);
}

// ---------------------------------------------------------------------------
// A-resident fp16 GEMM: C[128, ntiles*128] = A[128,256](fp32) @ Bt^T + bias
// A tile converted to fp16 and held in SMEM (64KB, 8 swizzled 32-half chunks);
// CTA loops over N-tiles internally so A is read from DRAM exactly once.
// B streamed via cp.async double buffer (2 x 8KB); weights stay L2-resident.
// 8 warps (2M x 4N), warp tile 64x32 per N-tile.
// ---------------------------------------------------------------------------
#define SMEM_A_BYTES 65536
#define B_STAGE 8192

template<bool HALF_OUT>
__global__ __launch_bounds__(256, 2)
void gemm_f16(const float* __restrict__ A, const __half* __restrict__ Bt,
              const float* __restrict__ bias, void* __restrict__ Cv,
              int ldc, int ntiles)
{
    extern __shared__ char smc[];
    const uint32_t sb = smem_u32(smc);          // A region
    const uint32_t sB = sb + SMEM_A_BYTES;      // B stages
    const int tid = threadIdx.x, wid = tid >> 5, lane = tid & 31;
    const int bm = blockIdx.x << 7;
    const int wm = (wid >> 2) << 6;
    const int wn = (wid & 3) << 5;

    const float* Ag = A + (size_t)bm * 256;
    const int arow = tid >> 1, ahalf = tid & 1;

    auto cpB = [&](int g, uint32_t dst) {       // global chunk g = bn*8 + c
        const int bnp = g >> 3, cp = g & 7;
        #pragma unroll
        for (int j = 0; j < 2; ++j) {
            const int kh = ahalf * 16 + j * 8;
            cp16(dst + swz(arow, kh),
                 Bt + (size_t)(bnp * 128 + arow) * 256 + cp * 32 + kh);
        }
        CP_COMMIT();
    };

    const int G = ntiles * 8;

    // prologue: B chunks 0,1 in flight, then convert-load all of A
    cpB(0, sB);
    cpB(1, sB + B_STAGE);
    #pragma unroll
    for (int c = 0; c < 8; ++c) {
        const float* p = Ag + (size_t)arow * 256 + c * 32 + ahalf * 16;
        #pragma unroll
        for (int j = 0; j < 4; ++j) {
            float4 v = *(const float4*)(p + j * 4);
            const int kh = ahalf * 16 + j * 4;
            uint32_t h01 = h2_bits(__floats2half2_rn(v.x, v.y));
            uint32_t h23 = h2_bits(__floats2half2_rn(v.z, v.w));
            asm volatile("st.shared.v2.b32 [%0], {%1, %2};"
                :: "r"(sb + c * B_STAGE + swz(arow, kh)), "r"(h01), "r"(h23)
                : "memory");
        }
    }

    // per-warp ldmatrix lane offsets (within a 32-half chunk; ks=1 -> XOR 32)
    uint32_t aoff[4], boff[2];
    {
        const int ar = (lane & 15), akh = (lane >> 4) * 8;
        #pragma unroll
        for (int mt = 0; mt < 4; ++mt) aoff[mt] = swz(wm + mt * 16 + ar, akh);
        const int br0 = (lane & 7) + ((lane >> 4) << 3), bkh = lane & 8;
        #pragma unroll
        for (int n2 = 0; n2 < 2; ++n2) boff[n2] = swz(wn + n2 * 16 + br0, bkh);
    }
    const int gm = lane >> 2, gn2 = (lane & 3) * 2;

    for (int bn = 0; bn < ntiles; ++bn) {
        float acc[4][4][4] = {};
        #pragma unroll
        for (int c = 0; c < 8; ++c) {
            const int g = bn * 8 + c;
            const uint32_t stA = sb + (uint32_t)c * B_STAGE;
            const uint32_t stB = sB + (uint32_t)(g & 1) * B_STAGE;
            if (g == G - 1) CP_WAIT(0); else CP_WAIT(1);
            __syncthreads();

            #pragma unroll
            for (int ks = 0; ks < 2; ++ks) {
                const uint32_t xo = ks * 32;
                uint32_t afr[4][4], bfr[2][4];
                #pragma unroll
                for (int mt = 0; mt < 4; ++mt) ldm4(afr[mt], stA + (aoff[mt] ^ xo));
                #pragma unroll
                for (int n2 = 0; n2 < 2; ++n2) ldm4(bfr[n2], stB + (boff[n2] ^ xo));
                #pragma unroll
                for (int mt = 0; mt < 4; ++mt)
                    #pragma unroll
                    for (int nt = 0; nt < 4; ++nt)
                        mma_f16(acc[mt][nt], afr[mt], &bfr[nt >> 1][(nt & 1) * 2]);
            }
            __syncthreads();
            if (g + 2 < G) cpB(g + 2, stB);
        }

        // epilogue for this N-tile
        #pragma unroll
        for (int nt = 0; nt < 4; ++nt) {
            const int col = bn * 128 + wn + nt * 8 + gn2;
            const float b0 = bias[col], b1 = bias[col + 1];
            #pragma unroll
            for (int mt = 0; mt < 4; ++mt) {
                const int r0 = bm + wm + mt * 16 + gm;
                if (HALF_OUT) {
                    __half* C = (__half*)Cv;
                    *(__half2*)(C + (size_t)r0 * ldc + col) =
                        __floats2half2_rn(acc[mt][nt][0] + b0, acc[mt][nt][1] + b1);
                    *(__half2*)(C + (size_t)(r0 + 8) * ldc + col) =
                        __floats2half2_rn(acc[mt][nt][2] + b0, acc[mt][nt][3] + b1);
                } else {
                    float* C = (float*)Cv;
                    float2 o0 = { acc[mt][nt][0] + b0, acc[mt][nt][1] + b1 };
                    float2 o1 = { acc[mt][nt][2] + b0, acc[mt][nt][3] + b1 };
                    *(float2*)(C + (size_t)r0 * ldc + col) = o0;
                    *(float2*)(C + (size_t)(r0 + 8) * ldc + col) = o1;
                }
            }
        }
    }
}

// ---------------------------------------------------------------------------
// Deformable sampling (unchanged): block = 1 query (128 thr, 4 warps).
// ---------------------------------------------------------------------------
__global__ __launch_bounds__(128)
void msda_sample2(const __half* __restrict__ value,   // [B, Lin, 8, 32] fp16
                  const float* __restrict__ offattn,  // [B*Lq, 384]
                  const float* __restrict__ refpts,   // [B, Lq, 4, 2]
                  const int*   __restrict__ spatial,  // [4, 2]
                  const int*   __restrict__ lstart,   // [4]
                  float* __restrict__ outcore)        // [B*Lq, 256]
{
    const int qg  = blockIdx.x;
    const int b   = qg / LEN_Q;
    const int tid = threadIdx.x, wid = tid >> 5, lane = tid & 31;

    __shared__ float s_ref[8];
    __shared__ int   s_H[4], s_W[4], s_S[4];
    __shared__ __align__(16) float s_par[8][17][8];   // [head][sample][4 idx | 4 w]

    if (tid < 4) {
        s_H[tid] = spatial[2 * tid];
        s_W[tid] = spatial[2 * tid + 1];
        s_S[tid] = lstart[tid];
    }
    if (tid < 8) s_ref[tid] = refpts[(size_t)qg * 8 + tid];
    __syncthreads();

    const float* oa = offattn + (size_t)qg * 384;

    {
        const int hh = lane >> 4, s = lane & 15;
        const int head = 2 * wid + hh, l = s >> 2;

        float logit = oa[256 + head * 16 + s];
        float mx = logit;
        #pragma unroll
        for (int d = 8; d; d >>= 1) mx = fmaxf(mx, __shfl_xor_sync(0xffffffffu, mx, d));
        float e = expf(logit - mx);
        float sum = e;
        #pragma unroll
        for (int d = 8; d; d >>= 1) sum += __shfl_xor_sync(0xffffffffu, sum, d);
        const float aw = e / sum;

        const int H = s_H[l], W = s_W[l], st = s_S[l];
        const float Wf = (float)W, Hf = (float)H;
        const float ox = oa[head * 32 + 2 * s];
        const float oy = oa[head * 32 + 2 * s + 1];
        const float lx = s_ref[2 * l]     + ox / Wf;
        const float ly = s_ref[2 * l + 1] + oy / Hf;
        const float x = lx * Wf - 0.5f;
        const float y = ly * Hf - 0.5f;
        const float x0f = floorf(x), y0f = floorf(y);
        const float fx = x - x0f, fy = y - y0f;
        const int x0 = (int)x0f, y0 = (int)y0f;
        const int x1 = x0 + 1, y1 = y0 + 1;

        const float vx0 = (x0 >= 0 && x0 < W) ? 1.f : 0.f;
        const float vx1 = (x1 >= 0 && x1 < W) ? 1.f : 0.f;
        const float vy0 = (y0 >= 0 && y0 < H) ? 1.f : 0.f;
        const float vy1 = (y1 >= 0 && y1 < H) ? 1.f : 0.f;
        const int cx0 = min(max(x0, 0), W - 1), cx1 = min(max(x1, 0), W - 1);
        const int cy0 = min(max(y0, 0), H - 1), cy1 = min(max(y1, 0), H - 1);

        float* p = s_par[head][s];
        p[0] = __int_as_float(st + cy0 * W + cx0);
        p[1] = __int_as_float(st + cy0 * W + cx1);
        p[2] = __int_as_float(st + cy1 * W + cx0);
        p[3] = __int_as_float(st + cy1 * W + cx1);
        p[4] = aw * (1.f - fx) * (1.f - fy) * vx0 * vy0;
        p[5] = aw * fx * (1.f - fy) * vx1 * vy0;
        p[6] = aw * (1.f - fx) * fy * vx0 * vy1;
        p[7] = aw * fx * fy * vx1 * vy1;
    }
    __syncwarp();

    const int hh = lane >> 4, head = 2 * wid + hh, ch2 = lane & 15;
    const __half2* vb =
        (const __half2*)(value + (size_t)b * LEN_IN * 256 + head * 32) + ch2;

    float ax = 0.f, ay = 0.f;
    #pragma unroll
    for (int s = 0; s < 16; ++s) {
        const float4 pi = *(const float4*)&s_par[head][s][0];
        const float4 pw = *(const float4*)&s_par[head][s][4];
        const float2 v0 = __half22float2(vb[(size_t)__float_as_int(pi.x) * 128]);
        const float2 v1 = __half22float2(vb[(size_t)__float_as_int(pi.y) * 128]);
        const float2 v2 = __half22float2(vb[(size_t)__float_as_int(pi.z) * 128]);
        const float2 v3 = __half22float2(vb[(size_t)__float_as_int(pi.w) * 128]);
        ax += pw.x * v0.x + pw.y * v1.x + pw.z * v2.x + pw.w * v3.x;
        ay += pw.x * v0.y + pw.y * v1.y + pw.z * v2.y + pw.w * v3.y;
    }
    float2 o = { ax, ay };
    *(float2*)(outcore + (size_t)qg * 256 + head * 32 + 2 * ch2) = o;
}

// ---------------------------------------------------------------------------
extern "C" void kernel_launch(void* const* d_in, const int* in_sizes, int n_in,
                              void* d_out, int out_size)
{
    const float* query   = (const float*)d_in[0];
    const float* refpts  = (const float*)d_in[1];
    const float* input   = (const float*)d_in[2];
    const int*   spatial = (const int*)  d_in[3];
    const int*   lstart  = (const int*)  d_in[4];
    const float* W_off   = (const float*)d_in[5];
    const float* b_off   = (const float*)d_in[6];
    const float* W_attn  = (const float*)d_in[7];
    const float* b_attn  = (const float*)d_in[8];
    const float* W_val   = (const float*)d_in[9];
    const float* b_val   = (const float*)d_in[10];
    const float* W_out   = (const float*)d_in[11];
    const float* b_out   = (const float*)d_in[12];
    float* out = (float*)d_out;

    __half *value, *wt;
    float *offattn, *outcore, *bias_oa;
    cudaGetSymbolAddress((void**)&value,   g_value);
    cudaGetSymbolAddress((void**)&offattn, g_offattn);
    cudaGetSymbolAddress((void**)&outcore, g_outcore);
    cudaGetSymbolAddress((void**)&wt,      g_wt16);
    cudaGetSymbolAddress((void**)&bias_oa, g_bias_oa);
    __half* wt_val     = wt;
    __half* wt_offattn = wt + 65536;
    __half* wt_out     = wt + 65536 + 98304;

    const size_t smem = SMEM_A_BYTES + 2 * B_STAGE;   // 81920 B
    cudaFuncSetAttribute((const void*)gemm_f16<false>,
        cudaFuncAttributeMaxDynamicSharedMemorySize, (int)smem);
    cudaFuncSetAttribute((const void*)gemm_f16<true>,
        cudaFuncAttributeMaxDynamicSharedMemorySize, (int)smem);

    transpose_all<<<dim3(12, 8, 3), dim3(32, 8)>>>(
        W_val, W_off, W_attn, W_out, b_off, b_attn, wt, bias_oa);

    const int MT = NQ / 128;   // 680

    // value projection -> fp16 (N=256, 2 tiles)
    gemm_f16<true><<<MT, 256, smem>>>(input, wt_val, b_val, value, 256, 2);
    // fused offsets + attn logits (N=384, 3 tiles)
    gemm_f16<false><<<MT, 256, smem>>>(query, wt_offattn, bias_oa, offattn, 384, 3);

    msda_sample2<<<NQ, 128>>>(value, offattn, refpts, spatial, lstart, outcore);

    gemm_f16<false><<<MT, 256, smem>>>(outcore, wt_out, b_out, out, 256, 2);
}